// round 15
// baseline (speedup 1.0000x reference)
#include <cuda_runtime.h>
#include <cuda_fp16.h>
#include <cstdint>

// Problem sizes (fixed by the dataset)
#define TOK 32768
#define DD  1024
#define UU  1024

// ---------------- scratch (device globals; no allocs allowed) ----------------
__device__ __align__(1024) __half g_xq[(size_t)TOK * DD];   // sign(x) as fp16 +/-1, [TOK, DD] row-major
__device__ __align__(1024) __half g_wt[(size_t)UU * DD];    // W_comb transposed: [U, D] K-major fp16
__device__ float g_beta[TOK];

// ---------------- helpers ----------------
__device__ __forceinline__ uint32_t smem_u32(const void* p) {
    uint32_t a;
    asm("{ .reg .u64 t; cvta.to.shared.u64 t, %1; cvt.u32.u64 %0, t; }" : "=r"(a) : "l"(p));
    return a;
}
__device__ __forceinline__ void cp16(uint32_t dst, const void* src) {
    asm volatile("cp.async.cg.shared.global [%0], [%1], 16;" :: "r"(dst), "l"(src));
}
__device__ __forceinline__ uint32_t swz(uint32_t row, uint32_t chunk) {
    return row * 128u + ((chunk ^ (row & 7u)) * 16u);
}
__device__ __forceinline__ void ldsm4(uint32_t& r0, uint32_t& r1, uint32_t& r2, uint32_t& r3, uint32_t addr) {
    asm volatile("ldmatrix.sync.aligned.m8n8.x4.shared.b16 {%0,%1,%2,%3}, [%4];"
        : "=r"(r0), "=r"(r1), "=r"(r2), "=r"(r3) : "r"(addr));
}
__device__ __forceinline__ void mma16816(float* d, const uint32_t* a, const uint32_t* b) {
    asm volatile(
        "mma.sync.aligned.m16n8k16.row.col.f32.f16.f16.f32 "
        "{%0,%1,%2,%3}, {%4,%5,%6,%7}, {%8,%9}, {%0,%1,%2,%3};"
        : "+f"(d[0]), "+f"(d[1]), "+f"(d[2]), "+f"(d[3])
        : "r"(a[0]), "r"(a[1]), "r"(a[2]), "r"(a[3]), "r"(b[0]), "r"(b[1]));
}

#define MBAR_INIT(a, c) \
    asm volatile("mbarrier.init.shared.b64 [%0], %1;" :: "r"(a), "r"(c) : "memory")
#define MBAR_ARRIVE(a) \
    asm volatile("mbarrier.arrive.shared.b64 _, [%0];" :: "r"(a) : "memory")
// .noinc: the completion-arrive consumes one preset slot (default form nets zero).
#define CPASYNC_MBAR_ARRIVE(a) \
    asm volatile("cp.async.mbarrier.arrive.noinc.shared.b64 [%0];" :: "r"(a) : "memory")

#define MBAR_WAIT(a, ph) do {                                                      \
    uint32_t _m = (a); uint32_t _p = (ph); uint32_t _d;                            \
    asm volatile("{\n\t.reg .pred p;\n\t"                                          \
        "mbarrier.try_wait.parity.acquire.cta.shared::cta.b64 p, [%1], %2;\n\t"    \
        "selp.b32 %0,1,0,p;\n\t}"                                                  \
        : "=r"(_d) : "r"(_m), "r"(_p) : "memory");                                 \
    if (!_d) {                                                                     \
        asm volatile("{\n\t.reg .pred P1;\n\t"                                     \
            "W%=:\n\t"                                                             \
            "mbarrier.try_wait.parity.acquire.cta.shared::cta.b64 P1, [%0], %1, 0x989680;\n\t" \
            "@P1 bra.uni D%=;\n\t"                                                 \
            "bra.uni W%=;\n\t"                                                     \
            "D%=:\n\t}"                                                            \
            :: "r"(_m), "r"(_p) : "memory");                                       \
    }                                                                              \
} while (0)

__device__ __forceinline__ uint32_t sign_h(float v) {
    return v >= 0.0f ? 0x3C00u : 0xBC00u;   // +1.0h / -1.0h
}

// ---------------- kernel 1 (fused): quantize x + beta, and build W_comb^T ----------------
__global__ __launch_bounds__(128) void prep_kernel(
    const float* __restrict__ x,
    const float* __restrict__ k0, const float* __restrict__ k1, const float* __restrict__ k2,
    const float* __restrict__ a0, const float* __restrict__ a1, const float* __restrict__ a2)
{
    int t = threadIdx.x;
    if (blockIdx.x < TOK) {
        int row = blockIdx.x;
        const float4* xr = reinterpret_cast<const float4*>(x + (size_t)row * DD);
        float4 a = xr[2 * t];
        float4 b = xr[2 * t + 1];
        float s = fabsf(a.x) + fabsf(a.y) + fabsf(a.z) + fabsf(a.w)
                + fabsf(b.x) + fabsf(b.y) + fabsf(b.z) + fabsf(b.w);

        uint4 pk;
        pk.x = sign_h(a.x) | (sign_h(a.y) << 16);
        pk.y = sign_h(a.z) | (sign_h(a.w) << 16);
        pk.z = sign_h(b.x) | (sign_h(b.y) << 16);
        pk.w = sign_h(b.z) | (sign_h(b.w) << 16);
        reinterpret_cast<uint4*>(g_xq)[(size_t)row * 128 + t] = pk;

        #pragma unroll
        for (int o = 16; o > 0; o >>= 1) s += __shfl_xor_sync(0xFFFFFFFFu, s, o);
        __shared__ float ws[4];
        if ((t & 31) == 0) ws[t >> 5] = s;
        __syncthreads();
        if (t == 0) g_beta[row] = (ws[0] + ws[1] + ws[2] + ws[3]) * (1.0f / 1024.0f);
    } else {
        int b = blockIdx.x - TOK;
        int u0 = (b & 31) * 32;
        int d0 = (b >> 5) * 32;
        __shared__ float tile[32][33];
        int tx = t & 31;
        int ty4 = t >> 5;
        int u = u0 + tx;
        float A0 = a0[u], A1 = a1[u], A2 = a2[u];
        #pragma unroll
        for (int r = 0; r < 8; r++) {
            int d = d0 + ty4 * 8 + r;
            size_t idx = (size_t)d * UU + u;
            float w = (k0[idx] >= 0.0f ? A0 : -A0)
                    + (k1[idx] >= 0.0f ? A1 : -A1)
                    + (k2[idx] >= 0.0f ? A2 : -A2);
            tile[ty4 * 8 + r][tx] = w;
        }
        __syncthreads();
        #pragma unroll
        for (int r = 0; r < 8; r++) {
            int uo = u0 + ty4 * 8 + r;
            int dd = d0 + tx;
            g_wt[(size_t)uo * DD + dd] = __float2half(tile[tx][ty4 * 8 + r]);
        }
    }
}

// ---------------- kernel 2: HMMA GEMM, 2 CTAs/SM, mbarrier pipeline ----------------
// CTA tile 128x128, 256 threads (8 warps, 4m x 2n, warp tile 32x64), BK=64, 3 stages.
// Iteration-level fragment pipelining: the full-wait for stage s+1 and the LDSM of
// its k0 fragments live in the k16==3 slot of iter s, so the MMA stream never breaks
// at iteration boundaries (fragments flow across iters in a persistent double buffer).
static constexpr int BM = 128, BN = 128, BK = 64;
static constexpr int STAGES = 3;
static constexpr int A_BYTES = BM * BK * 2;              // 16384
static constexpr int B_BYTES = BN * BK * 2;              // 16384
static constexpr int STG_BYTES = A_BYTES + B_BYTES;      // 32768
static constexpr int SMEM_STAGE0 = 1024;                 // mbarriers live below
static constexpr int SMEM_TOTAL = SMEM_STAGE0 + STAGES * STG_BYTES;  // 99328
static constexpr int KITERS = DD / BK;                   // 16
static constexpr int ROWB = DD * 2;                      // 2048 B per gmem row
static constexpr int CH32 = 32 * ROWB;                   // 65536: 32-row block stride

__global__ __launch_bounds__(256, 2) void gemm_kernel(float* __restrict__ out) {
    extern __shared__ char smem[];
    uint32_t sb = smem_u32(smem);
    int tid = threadIdx.x;
    int wid = tid >> 5, lane = tid & 31;
    int m0 = (int)(blockIdx.x >> 3) * BM;
    int n0 = (int)(blockIdx.x & 7) * BN;
    int wrow = (wid & 3) * 32;
    int wcol = (wid >> 2) * 64;

    uint32_t mb_full  = sb;        // full[s] at sb + s*8
    uint32_t mb_empty = sb + 32;   // empty[s] at sb + 32 + s*8
    if (tid == 0) {
        #pragma unroll
        for (int s = 0; s < STAGES; s++) {
            MBAR_INIT(mb_full  + s * 8, 256);
            MBAR_INIT(mb_empty + s * 8, 256);
        }
    }
    __syncthreads();

    // affine load bases: thread covers rows {r0, r0+32, r0+64, r0+96}, 16B chunk c
    uint32_t r0 = (uint32_t)tid >> 3, c = (uint32_t)tid & 7;
    const char* pA = reinterpret_cast<const char*>(g_xq) + (size_t)(m0 + (int)r0) * ROWB + c * 16;
    const char* pB = reinterpret_cast<const char*>(g_wt) + (size_t)(n0 + (int)r0) * ROWB + c * 16;
    uint32_t dst0 = sb + SMEM_STAGE0 + swz(r0, c);

    // LDSM source geometry
    uint32_t a_row = (uint32_t)(wrow + (lane & 15));
    uint32_t a_ch0 = (uint32_t)(lane >> 4);
    uint32_t b_row = (uint32_t)(wcol + (lane & 7) + (lane >> 4) * 8);
    uint32_t b_ch0 = (uint32_t)((lane >> 3) & 1);

    uint32_t pf = 0;   // full parity bits (consumer starts 0)
    uint32_t pe = 7;   // empty parity bits (producer starts 1)

#define PRODUCE(slot) do {                                                         \
        MBAR_WAIT(mb_empty + (slot) * 8, (pe >> (slot)) & 1);                      \
        pe ^= (1u << (slot));                                                      \
        uint32_t d_ = dst0 + (uint32_t)(slot) * STG_BYTES;                         \
        _Pragma("unroll")                                                          \
        for (int i_ = 0; i_ < 4; i_++) cp16(d_ + 4096u * i_,           pA + CH32 * i_); \
        _Pragma("unroll")                                                          \
        for (int i_ = 0; i_ < 4; i_++) cp16(d_ + A_BYTES + 4096u * i_, pB + CH32 * i_); \
        CPASYNC_MBAR_ARRIVE(mb_full + (slot) * 8);                                 \
        pA += 128; pB += 128;                                                      \
    } while (0)

#define LDSM_A(buf, sa_, ch_)                                                       \
        _Pragma("unroll")                                                           \
        for (int mb_ = 0; mb_ < 2; mb_++)                                           \
            ldsm4(a[buf][mb_][0], a[buf][mb_][1], a[buf][mb_][2], a[buf][mb_][3],   \
                  (sa_) + swz(a_row + mb_ * 16, (ch_)))
#define LDSM_B(buf, sbb_, ch_)                                                      \
        _Pragma("unroll")                                                           \
        for (int nb_ = 0; nb_ < 4; nb_++)                                           \
            ldsm4(b[buf][nb_][0], b[buf][nb_][1], b[buf][nb_][2], b[buf][nb_][3],   \
                  (sbb_) + swz(b_row + nb_ * 16, (ch_)))
#define MMA_ALL(buf)                                                                \
        _Pragma("unroll")                                                           \
        for (int mb_ = 0; mb_ < 2; mb_++)                                           \
            _Pragma("unroll")                                                       \
            for (int nb_ = 0; nb_ < 8; nb_++)                                       \
                mma16816(acc[mb_][nb_], a[buf][mb_], &b[buf][nb_ >> 1][(nb_ & 1) * 2])

    // prologue: produce K-chunks 0, 1; wait stage 0; preload its k0 fragments
    PRODUCE(0);
    PRODUCE(1);

    float acc[2][8][4];
    #pragma unroll
    for (int i = 0; i < 2; i++)
        #pragma unroll
        for (int j = 0; j < 8; j++)
            #pragma unroll
            for (int k = 0; k < 4; k++) acc[i][j][k] = 0.0f;

    uint32_t a[2][2][4], b[2][4][4];

    MBAR_WAIT(mb_full + 0, 0);
    pf ^= 1u;
    LDSM_A(0, sb + SMEM_STAGE0, a_ch0);
    LDSM_B(0, sb + SMEM_STAGE0 + A_BYTES, b_ch0);

    int s = 0, sj = 2;
    for (int it = 0; it < KITERS; ++it) {
        uint32_t sa  = sb + SMEM_STAGE0 + (uint32_t)s * STG_BYTES;
        uint32_t sbb = sa + A_BYTES;

        // k16 = 0: LDSM k1; MMA k0 (fragments already resident)
        LDSM_A(1, sa, a_ch0 + 2);
        LDSM_B(1, sbb, b_ch0 + 2);
        MMA_ALL(0);

        // produce chunk it+2 behind the queued MMAs
        if (it < KITERS - 2) {
            PRODUCE(sj);
            sj = (sj == 2) ? 0 : sj + 1;
        }

        // k16 = 1: LDSM k2; MMA k1
        LDSM_A(0, sa, a_ch0 + 4);
        LDSM_B(0, sbb, b_ch0 + 4);
        MMA_ALL(1);

        // k16 = 2: LDSM k3 (last read of stage s); release stage; MMA k2
        LDSM_A(1, sa, a_ch0 + 6);
        LDSM_B(1, sbb, b_ch0 + 6);
        MBAR_ARRIVE(mb_empty + s * 8);
        MMA_ALL(0);

        // k16 = 3: wait next stage + preload its k0 fragments; MMA k3
        if (it < KITERS - 1) {
            int sn = (s == 2) ? 0 : s + 1;
            MBAR_WAIT(mb_full + sn * 8, (pf >> sn) & 1);
            pf ^= (1u << sn);
            uint32_t sa2  = sb + SMEM_STAGE0 + (uint32_t)sn * STG_BYTES;
            LDSM_A(0, sa2, a_ch0);
            LDSM_B(0, sa2 + A_BYTES, b_ch0);
            s = sn;
        }
        MMA_ALL(1);
    }

    // epilogue: scale rows by beta and store
    int group = lane >> 2, t4 = lane & 3;
    #pragma unroll
    for (int mb = 0; mb < 2; mb++) {
        int r0e = m0 + wrow + mb * 16 + group;
        float b0 = g_beta[r0e];
        float b1 = g_beta[r0e + 8];
        float* o0 = out + (size_t)r0e * UU + n0 + wcol + t4 * 2;
        float* o1 = o0 + (size_t)8 * UU;
        #pragma unroll
        for (int nb = 0; nb < 8; nb++) {
            float2 v0 = make_float2(acc[mb][nb][0] * b0, acc[mb][nb][1] * b0);
            float2 v1 = make_float2(acc[mb][nb][2] * b1, acc[mb][nb][3] * b1);
            *reinterpret_cast<float2*>(o0 + nb * 8) = v0;
            *reinterpret_cast<float2*>(o1 + nb * 8) = v1;
        }
    }
#undef PRODUCE
#undef LDSM_A
#undef LDSM_B
#undef MMA_ALL
}

// ---------------- launch ----------------
extern "C" void kernel_launch(void* const* d_in, const int* in_sizes, int n_in,
                              void* d_out, int out_size) {
    const float* x  = (const float*)d_in[0];
    const float* k0 = (const float*)d_in[1];
    const float* k1 = (const float*)d_in[2];
    const float* k2 = (const float*)d_in[3];
    const float* a0 = (const float*)d_in[4];
    const float* a1 = (const float*)d_in[5];
    const float* a2 = (const float*)d_in[6];
    float* out = (float*)d_out;

    prep_kernel<<<TOK + 1024, 128>>>(x, k0, k1, k2, a0, a1, a2);

    cudaFuncSetAttribute(gemm_kernel, cudaFuncAttributeMaxDynamicSharedMemorySize, SMEM_TOTAL);
    gemm_kernel<<<(TOK / BM) * (UU / BN), 256, SMEM_TOTAL>>>(out);
}

// round 16
// speedup vs baseline: 1.0782x; 1.0782x over previous
#include <cuda_runtime.h>
#include <cuda_fp16.h>
#include <cstdint>

// Problem sizes (fixed by the dataset)
#define TOK 32768
#define DD  1024
#define UU  1024

// ---------------- scratch (device globals; no allocs allowed) ----------------
__device__ __align__(1024) __half g_xq[(size_t)TOK * DD];   // sign(x) as fp16 +/-1, [TOK, DD] row-major
__device__ __align__(1024) __half g_wt[(size_t)UU * DD];    // W_comb transposed: [U, D] K-major fp16
__device__ float g_beta[TOK];

// ---------------- helpers ----------------
__device__ __forceinline__ uint32_t smem_u32(const void* p) {
    uint32_t a;
    asm("{ .reg .u64 t; cvta.to.shared.u64 t, %1; cvt.u32.u64 %0, t; }" : "=r"(a) : "l"(p));
    return a;
}
__device__ __forceinline__ void cp16(uint32_t dst, const void* src) {
    asm volatile("cp.async.cg.shared.global [%0], [%1], 16;" :: "r"(dst), "l"(src));
}
__device__ __forceinline__ uint32_t swz(uint32_t row, uint32_t chunk) {
    return row * 128u + ((chunk ^ (row & 7u)) * 16u);
}
__device__ __forceinline__ void ldsm4(uint32_t& r0, uint32_t& r1, uint32_t& r2, uint32_t& r3, uint32_t addr) {
    asm volatile("ldmatrix.sync.aligned.m8n8.x4.shared.b16 {%0,%1,%2,%3}, [%4];"
        : "=r"(r0), "=r"(r1), "=r"(r2), "=r"(r3) : "r"(addr));
}
__device__ __forceinline__ void mma16816(float* d, const uint32_t* a, const uint32_t* b) {
    asm volatile(
        "mma.sync.aligned.m16n8k16.row.col.f32.f16.f16.f32 "
        "{%0,%1,%2,%3}, {%4,%5,%6,%7}, {%8,%9}, {%0,%1,%2,%3};"
        : "+f"(d[0]), "+f"(d[1]), "+f"(d[2]), "+f"(d[3])
        : "r"(a[0]), "r"(a[1]), "r"(a[2]), "r"(a[3]), "r"(b[0]), "r"(b[1]));
}

#define MBAR_INIT(a, c) \
    asm volatile("mbarrier.init.shared.b64 [%0], %1;" :: "r"(a), "r"(c) : "memory")
#define MBAR_ARRIVE(a) \
    asm volatile("mbarrier.arrive.shared.b64 _, [%0];" :: "r"(a) : "memory")
// .noinc: the completion-arrive consumes one preset slot (default form nets zero).
#define CPASYNC_MBAR_ARRIVE(a) \
    asm volatile("cp.async.mbarrier.arrive.noinc.shared.b64 [%0];" :: "r"(a) : "memory")

#define MBAR_WAIT(a, ph) do {                                                      \
    uint32_t _m = (a); uint32_t _p = (ph); uint32_t _d;                            \
    asm volatile("{\n\t.reg .pred p;\n\t"                                          \
        "mbarrier.try_wait.parity.acquire.cta.shared::cta.b64 p, [%1], %2;\n\t"    \
        "selp.b32 %0,1,0,p;\n\t}"                                                  \
        : "=r"(_d) : "r"(_m), "r"(_p) : "memory");                                 \
    if (!_d) {                                                                     \
        asm volatile("{\n\t.reg .pred P1;\n\t"                                     \
            "W%=:\n\t"                                                             \
            "mbarrier.try_wait.parity.acquire.cta.shared::cta.b64 P1, [%0], %1, 0x989680;\n\t" \
            "@P1 bra.uni D%=;\n\t"                                                 \
            "bra.uni W%=;\n\t"                                                     \
            "D%=:\n\t}"                                                            \
            :: "r"(_m), "r"(_p) : "memory");                                       \
    }                                                                              \
} while (0)

__device__ __forceinline__ uint32_t sign_h(float v) {
    return v >= 0.0f ? 0x3C00u : 0xBC00u;   // +1.0h / -1.0h
}

// ---------------- kernel 1 (fused): quantize x + beta, and build W_comb^T ----------------
__global__ __launch_bounds__(128) void prep_kernel(
    const float* __restrict__ x,
    const float* __restrict__ k0, const float* __restrict__ k1, const float* __restrict__ k2,
    const float* __restrict__ a0, const float* __restrict__ a1, const float* __restrict__ a2)
{
    int t = threadIdx.x;
    if (blockIdx.x < TOK) {
        int row = blockIdx.x;
        const float4* xr = reinterpret_cast<const float4*>(x + (size_t)row * DD);
        float4 a = xr[2 * t];
        float4 b = xr[2 * t + 1];
        float s = fabsf(a.x) + fabsf(a.y) + fabsf(a.z) + fabsf(a.w)
                + fabsf(b.x) + fabsf(b.y) + fabsf(b.z) + fabsf(b.w);

        uint4 pk;
        pk.x = sign_h(a.x) | (sign_h(a.y) << 16);
        pk.y = sign_h(a.z) | (sign_h(a.w) << 16);
        pk.z = sign_h(b.x) | (sign_h(b.y) << 16);
        pk.w = sign_h(b.z) | (sign_h(b.w) << 16);
        reinterpret_cast<uint4*>(g_xq)[(size_t)row * 128 + t] = pk;

        #pragma unroll
        for (int o = 16; o > 0; o >>= 1) s += __shfl_xor_sync(0xFFFFFFFFu, s, o);
        __shared__ float ws[4];
        if ((t & 31) == 0) ws[t >> 5] = s;
        __syncthreads();
        if (t == 0) g_beta[row] = (ws[0] + ws[1] + ws[2] + ws[3]) * (1.0f / 1024.0f);
    } else {
        int b = blockIdx.x - TOK;
        int u0 = (b & 31) * 32;
        int d0 = (b >> 5) * 32;
        __shared__ float tile[32][33];
        int tx = t & 31;
        int ty4 = t >> 5;
        int u = u0 + tx;
        float A0 = a0[u], A1 = a1[u], A2 = a2[u];
        #pragma unroll
        for (int r = 0; r < 8; r++) {
            int d = d0 + ty4 * 8 + r;
            size_t idx = (size_t)d * UU + u;
            float w = (k0[idx] >= 0.0f ? A0 : -A0)
                    + (k1[idx] >= 0.0f ? A1 : -A1)
                    + (k2[idx] >= 0.0f ? A2 : -A2);
            tile[ty4 * 8 + r][tx] = w;
        }
        __syncthreads();
        #pragma unroll
        for (int r = 0; r < 8; r++) {
            int uo = u0 + ty4 * 8 + r;
            int dd = d0 + tx;
            g_wt[(size_t)uo * DD + dd] = __float2half(tile[tx][ty4 * 8 + r]);
        }
    }
}

// ---------------- kernel 2: HMMA GEMM, 64x64 warp tiles (low crossbar traffic) ----------------
// CTA tile 128x128, 128 threads (4 warps, 2m x 2n, warp tile 64x64), BK=64, 3 stages,
// 2 CTAs/SM (256 threads/SM -> up to 255 regs/thread; acc=128 + frags=32 fits).
// Crossbar economy: per warp per k16, 8 LDSM feed 32 MMAs (A and B each read 2x) vs
// 6 LDSM per 16 MMAs before -> LDSM/SM-iter-pair 96KB -> 64KB; total crossbar ~1536 cyc
// < MMA 2048 cyc. R12's mbarrier full/empty protocol (counts 128).
static constexpr int BM = 128, BN = 128, BK = 64;
static constexpr int STAGES = 3;
static constexpr int A_BYTES = BM * BK * 2;              // 16384
static constexpr int B_BYTES = BN * BK * 2;              // 16384
static constexpr int STG_BYTES = A_BYTES + B_BYTES;      // 32768
static constexpr int SMEM_STAGE0 = 1024;                 // mbarriers live below
static constexpr int SMEM_TOTAL = SMEM_STAGE0 + STAGES * STG_BYTES;  // 99328
static constexpr int KITERS = DD / BK;                   // 16
static constexpr int ROWB = DD * 2;                      // 2048 B per gmem row
static constexpr int CH16 = 16 * ROWB;                   // 32768: 16-row block stride

__global__ __launch_bounds__(128, 2) void gemm_kernel(float* __restrict__ out) {
    extern __shared__ char smem[];
    uint32_t sb = smem_u32(smem);
    int tid = threadIdx.x;
    int wid = tid >> 5, lane = tid & 31;
    int m0 = (int)(blockIdx.x >> 3) * BM;
    int n0 = (int)(blockIdx.x & 7) * BN;
    int wrow = (wid & 1) * 64;              // 2 m-warps x 64 rows
    int wcol = (wid >> 1) * 64;             // 2 n-warps x 64 cols

    uint32_t mb_full  = sb;        // full[s] at sb + s*8
    uint32_t mb_empty = sb + 32;   // empty[s] at sb + 32 + s*8
    if (tid == 0) {
        #pragma unroll
        for (int s = 0; s < STAGES; s++) {
            MBAR_INIT(mb_full  + s * 8, 128);   // one cp.async noinc arrive per thread
            MBAR_INIT(mb_empty + s * 8, 128);   // one arrive per thread
        }
    }
    __syncthreads();

    // affine load bases: thread covers rows {r0 + 16i, i<8}, 16B chunk c
    uint32_t r0 = (uint32_t)tid >> 3, c = (uint32_t)tid & 7;   // r0 in [0,16)
    const char* pA = reinterpret_cast<const char*>(g_xq) + (size_t)(m0 + (int)r0) * ROWB + c * 16;
    const char* pB = reinterpret_cast<const char*>(g_wt) + (size_t)(n0 + (int)r0) * ROWB + c * 16;
    uint32_t dst0 = sb + SMEM_STAGE0 + swz(r0, c);             // +2048B per 16-row block

    // LDSM source geometry
    uint32_t a_row = (uint32_t)(wrow + (lane & 15));
    uint32_t a_ch0 = (uint32_t)(lane >> 4);
    uint32_t b_row = (uint32_t)(wcol + (lane & 7) + (lane >> 4) * 8);
    uint32_t b_ch0 = (uint32_t)((lane >> 3) & 1);

    uint32_t pf = 0;   // full parity bits (consumer starts 0)
    uint32_t pe = 7;   // empty parity bits (producer starts 1)

#define PRODUCE(slot) do {                                                         \
        MBAR_WAIT(mb_empty + (slot) * 8, (pe >> (slot)) & 1);                      \
        pe ^= (1u << (slot));                                                      \
        uint32_t d_ = dst0 + (uint32_t)(slot) * STG_BYTES;                         \
        _Pragma("unroll")                                                          \
        for (int i_ = 0; i_ < 8; i_++) cp16(d_ + 2048u * i_,           pA + CH16 * i_); \
        _Pragma("unroll")                                                          \
        for (int i_ = 0; i_ < 8; i_++) cp16(d_ + A_BYTES + 2048u * i_, pB + CH16 * i_); \
        CPASYNC_MBAR_ARRIVE(mb_full + (slot) * 8);                                 \
        pA += 128; pB += 128;                                                      \
    } while (0)

    // prologue: produce K-chunks 0, 1 into slots 0, 1
    PRODUCE(0);
    PRODUCE(1);

    float acc[4][8][4];
    #pragma unroll
    for (int i = 0; i < 4; i++)
        #pragma unroll
        for (int j = 0; j < 8; j++)
            #pragma unroll
            for (int k = 0; k < 4; k++) acc[i][j][k] = 0.0f;

    uint32_t a[4][4], b[4][4];
    int s = 0, sj = 2;   // consume slot, produce slot

    for (int it = 0; it < KITERS; ++it) {
        // ---- wait for iter it's data ----
        MBAR_WAIT(mb_full + s * 8, (pf >> s) & 1);
        pf ^= (1u << s);

        // ---- early produce: K-chunk it+2 into slot sj ----
        if (it < KITERS - 2) {
            PRODUCE(sj);
            sj = (sj == 2) ? 0 : sj + 1;
        }

        uint32_t sa  = sb + SMEM_STAGE0 + (uint32_t)s * STG_BYTES;
        uint32_t sbb = sa + A_BYTES;

        #pragma unroll
        for (int k16 = 0; k16 < 4; k16++) {
            uint32_t ach = a_ch0 + (uint32_t)k16 * 2;
            uint32_t bch = b_ch0 + (uint32_t)k16 * 2;
            #pragma unroll
            for (int mb = 0; mb < 4; mb++)
                ldsm4(a[mb][0], a[mb][1], a[mb][2], a[mb][3],
                      sa + swz(a_row + mb * 16, ach));
            #pragma unroll
            for (int nb16 = 0; nb16 < 4; nb16++)
                ldsm4(b[nb16][0], b[nb16][1], b[nb16][2], b[nb16][3],
                      sbb + swz(b_row + nb16 * 16, bch));
            if (k16 == 3) {
                // last LDSM of stage s issued -> release for refill
                MBAR_ARRIVE(mb_empty + s * 8);
            }
            #pragma unroll
            for (int mb = 0; mb < 4; mb++)
                #pragma unroll
                for (int nb = 0; nb < 8; nb++)
                    mma16816(acc[mb][nb], a[mb], &b[nb >> 1][(nb & 1) * 2]);
        }

        s = (s == 2) ? 0 : s + 1;
    }

    // epilogue: scale rows by beta and store
    int group = lane >> 2, t4 = lane & 3;
    #pragma unroll
    for (int mb = 0; mb < 4; mb++) {
        int r0e = m0 + wrow + mb * 16 + group;
        float b0 = g_beta[r0e];
        float b1 = g_beta[r0e + 8];
        float* o0 = out + (size_t)r0e * UU + n0 + wcol + t4 * 2;
        float* o1 = o0 + (size_t)8 * UU;
        #pragma unroll
        for (int nb = 0; nb < 8; nb++) {
            float2 v0 = make_float2(acc[mb][nb][0] * b0, acc[mb][nb][1] * b0);
            float2 v1 = make_float2(acc[mb][nb][2] * b1, acc[mb][nb][3] * b1);
            *reinterpret_cast<float2*>(o0 + nb * 8) = v0;
            *reinterpret_cast<float2*>(o1 + nb * 8) = v1;
        }
    }
#undef PRODUCE
}

// ---------------- launch ----------------
extern "C" void kernel_launch(void* const* d_in, const int* in_sizes, int n_in,
                              void* d_out, int out_size) {
    const float* x  = (const float*)d_in[0];
    const float* k0 = (const float*)d_in[1];
    const float* k1 = (const float*)d_in[2];
    const float* k2 = (const float*)d_in[3];
    const float* a0 = (const float*)d_in[4];
    const float* a1 = (const float*)d_in[5];
    const float* a2 = (const float*)d_in[6];
    float* out = (float*)d_out;

    prep_kernel<<<TOK + 1024, 128>>>(x, k0, k1, k2, a0, a1, a2);

    cudaFuncSetAttribute(gemm_kernel, cudaFuncAttributeMaxDynamicSharedMemorySize, SMEM_TOTAL);
    gemm_kernel<<<(TOK / BM) * (UU / BN), 128, SMEM_TOTAL>>>(out);
}

// round 17
// speedup vs baseline: 1.0788x; 1.0005x over previous
#include <cuda_runtime.h>
#include <cuda_fp16.h>
#include <cstdint>

// Problem sizes (fixed by the dataset)
#define TOK 32768
#define DD  1024
#define UU  1024

// ---------------- scratch (device globals; no allocs allowed) ----------------
__device__ __align__(1024) __half g_xq[(size_t)TOK * DD];   // sign(x) as fp16 +/-1, [TOK, DD] row-major
__device__ __align__(1024) __half g_wt[(size_t)UU * DD];    // W_comb transposed: [U, D] K-major fp16
__device__ float g_beta[TOK];

// ---------------- helpers ----------------
__device__ __forceinline__ uint32_t smem_u32(const void* p) {
    uint32_t a;
    asm("{ .reg .u64 t; cvta.to.shared.u64 t, %1; cvt.u32.u64 %0, t; }" : "=r"(a) : "l"(p));
    return a;
}
__device__ __forceinline__ void cp16(uint32_t dst, const void* src) {
    asm volatile("cp.async.cg.shared.global [%0], [%1], 16;" :: "r"(dst), "l"(src));
}
__device__ __forceinline__ uint32_t swz(uint32_t row, uint32_t chunk) {
    return row * 128u + ((chunk ^ (row & 7u)) * 16u);
}
__device__ __forceinline__ void ldsm4(uint32_t& r0, uint32_t& r1, uint32_t& r2, uint32_t& r3, uint32_t addr) {
    asm volatile("ldmatrix.sync.aligned.m8n8.x4.shared.b16 {%0,%1,%2,%3}, [%4];"
        : "=r"(r0), "=r"(r1), "=r"(r2), "=r"(r3) : "r"(addr));
}
__device__ __forceinline__ void mma16816(float* d, const uint32_t* a, const uint32_t* b) {
    asm volatile(
        "mma.sync.aligned.m16n8k16.row.col.f32.f16.f16.f32 "
        "{%0,%1,%2,%3}, {%4,%5,%6,%7}, {%8,%9}, {%0,%1,%2,%3};"
        : "+f"(d[0]), "+f"(d[1]), "+f"(d[2]), "+f"(d[3])
        : "r"(a[0]), "r"(a[1]), "r"(a[2]), "r"(a[3]), "r"(b[0]), "r"(b[1]));
}

#define MBAR_INIT(a, c) \
    asm volatile("mbarrier.init.shared.b64 [%0], %1;" :: "r"(a), "r"(c) : "memory")
#define MBAR_ARRIVE(a) \
    asm volatile("mbarrier.arrive.shared.b64 _, [%0];" :: "r"(a) : "memory")
// .noinc: the completion-arrive consumes one preset slot (default form nets zero).
#define CPASYNC_MBAR_ARRIVE(a) \
    asm volatile("cp.async.mbarrier.arrive.noinc.shared.b64 [%0];" :: "r"(a) : "memory")

#define MBAR_WAIT(a, ph) do {                                                      \
    uint32_t _m = (a); uint32_t _p = (ph); uint32_t _d;                            \
    asm volatile("{\n\t.reg .pred p;\n\t"                                          \
        "mbarrier.try_wait.parity.acquire.cta.shared::cta.b64 p, [%1], %2;\n\t"    \
        "selp.b32 %0,1,0,p;\n\t}"                                                  \
        : "=r"(_d) : "r"(_m), "r"(_p) : "memory");                                 \
    if (!_d) {                                                                     \
        asm volatile("{\n\t.reg .pred P1;\n\t"                                     \
            "W%=:\n\t"                                                             \
            "mbarrier.try_wait.parity.acquire.cta.shared::cta.b64 P1, [%0], %1, 0x989680;\n\t" \
            "@P1 bra.uni D%=;\n\t"                                                 \
            "bra.uni W%=;\n\t"                                                     \
            "D%=:\n\t}"                                                            \
            :: "r"(_m), "r"(_p) : "memory");                                       \
    }                                                                              \
} while (0)

__device__ __forceinline__ uint32_t sign_h(float v) {
    return v >= 0.0f ? 0x3C00u : 0xBC00u;   // +1.0h / -1.0h
}

// ---------------- kernel 1 (fused): quantize x + beta, and build W_comb^T ----------------
__global__ __launch_bounds__(128) void prep_kernel(
    const float* __restrict__ x,
    const float* __restrict__ k0, const float* __restrict__ k1, const float* __restrict__ k2,
    const float* __restrict__ a0, const float* __restrict__ a1, const float* __restrict__ a2)
{
    int t = threadIdx.x;
    if (blockIdx.x < TOK) {
        int row = blockIdx.x;
        const float4* xr = reinterpret_cast<const float4*>(x + (size_t)row * DD);
        float4 a = xr[2 * t];
        float4 b = xr[2 * t + 1];
        float s = fabsf(a.x) + fabsf(a.y) + fabsf(a.z) + fabsf(a.w)
                + fabsf(b.x) + fabsf(b.y) + fabsf(b.z) + fabsf(b.w);

        uint4 pk;
        pk.x = sign_h(a.x) | (sign_h(a.y) << 16);
        pk.y = sign_h(a.z) | (sign_h(a.w) << 16);
        pk.z = sign_h(b.x) | (sign_h(b.y) << 16);
        pk.w = sign_h(b.z) | (sign_h(b.w) << 16);
        reinterpret_cast<uint4*>(g_xq)[(size_t)row * 128 + t] = pk;

        #pragma unroll
        for (int o = 16; o > 0; o >>= 1) s += __shfl_xor_sync(0xFFFFFFFFu, s, o);
        __shared__ float ws[4];
        if ((t & 31) == 0) ws[t >> 5] = s;
        __syncthreads();
        if (t == 0) g_beta[row] = (ws[0] + ws[1] + ws[2] + ws[3]) * (1.0f / 1024.0f);
    } else {
        int b = blockIdx.x - TOK;
        int u0 = (b & 31) * 32;
        int d0 = (b >> 5) * 32;
        __shared__ float tile[32][33];
        int tx = t & 31;
        int ty4 = t >> 5;
        int u = u0 + tx;
        float A0 = a0[u], A1 = a1[u], A2 = a2[u];
        #pragma unroll
        for (int r = 0; r < 8; r++) {
            int d = d0 + ty4 * 8 + r;
            size_t idx = (size_t)d * UU + u;
            float w = (k0[idx] >= 0.0f ? A0 : -A0)
                    + (k1[idx] >= 0.0f ? A1 : -A1)
                    + (k2[idx] >= 0.0f ? A2 : -A2);
            tile[ty4 * 8 + r][tx] = w;
        }
        __syncthreads();
        #pragma unroll
        for (int r = 0; r < 8; r++) {
            int uo = u0 + ty4 * 8 + r;
            int dd = d0 + tx;
            g_wt[(size_t)uo * DD + dd] = __float2half(tile[tx][ty4 * 8 + r]);
        }
    }
}

// ---------------- kernel 2: HMMA GEMM, 64x64 warp tiles + fragment double buffer ----------------
// CTA tile 128x128, 128 threads (4 warps, 2m x 2n, warp tile 64x64), BK=64, 3 stages,
// 2 CTAs/SM. Crossbar-light (8 LDSM per 32 MMA per warp-k16). Fragments double-buffered:
// LDSM for k16+1 issues before the MMAs of k16, hiding the LDSM latency chain that
// limits the single-buffered version (R16: tensor 75.6%, L1 only 50%).
static constexpr int BM = 128, BN = 128, BK = 64;
static constexpr int STAGES = 3;
static constexpr int A_BYTES = BM * BK * 2;              // 16384
static constexpr int B_BYTES = BN * BK * 2;              // 16384
static constexpr int STG_BYTES = A_BYTES + B_BYTES;      // 32768
static constexpr int SMEM_STAGE0 = 1024;                 // mbarriers live below
static constexpr int SMEM_TOTAL = SMEM_STAGE0 + STAGES * STG_BYTES;  // 99328
static constexpr int KITERS = DD / BK;                   // 16
static constexpr int ROWB = DD * 2;                      // 2048 B per gmem row
static constexpr int CH16 = 16 * ROWB;                   // 32768: 16-row block stride

__global__ __launch_bounds__(128, 2) void gemm_kernel(float* __restrict__ out) {
    extern __shared__ char smem[];
    uint32_t sb = smem_u32(smem);
    int tid = threadIdx.x;
    int wid = tid >> 5, lane = tid & 31;
    int m0 = (int)(blockIdx.x >> 3) * BM;
    int n0 = (int)(blockIdx.x & 7) * BN;
    int wrow = (wid & 1) * 64;              // 2 m-warps x 64 rows
    int wcol = (wid >> 1) * 64;             // 2 n-warps x 64 cols

    uint32_t mb_full  = sb;        // full[s] at sb + s*8
    uint32_t mb_empty = sb + 32;   // empty[s] at sb + 32 + s*8
    if (tid == 0) {
        #pragma unroll
        for (int s = 0; s < STAGES; s++) {
            MBAR_INIT(mb_full  + s * 8, 128);   // one cp.async noinc arrive per thread
            MBAR_INIT(mb_empty + s * 8, 128);   // one arrive per thread
        }
    }
    __syncthreads();

    // affine load bases: thread covers rows {r0 + 16i, i<8}, 16B chunk c
    uint32_t r0 = (uint32_t)tid >> 3, c = (uint32_t)tid & 7;   // r0 in [0,16)
    const char* pA = reinterpret_cast<const char*>(g_xq) + (size_t)(m0 + (int)r0) * ROWB + c * 16;
    const char* pB = reinterpret_cast<const char*>(g_wt) + (size_t)(n0 + (int)r0) * ROWB + c * 16;
    uint32_t dst0 = sb + SMEM_STAGE0 + swz(r0, c);             // +2048B per 16-row block

    // LDSM source geometry
    uint32_t a_row = (uint32_t)(wrow + (lane & 15));
    uint32_t a_ch0 = (uint32_t)(lane >> 4);
    uint32_t b_row = (uint32_t)(wcol + (lane & 7) + (lane >> 4) * 8);
    uint32_t b_ch0 = (uint32_t)((lane >> 3) & 1);

    uint32_t pf = 0;   // full parity bits (consumer starts 0)
    uint32_t pe = 7;   // empty parity bits (producer starts 1)

#define PRODUCE(slot) do {                                                         \
        MBAR_WAIT(mb_empty + (slot) * 8, (pe >> (slot)) & 1);                      \
        pe ^= (1u << (slot));                                                      \
        uint32_t d_ = dst0 + (uint32_t)(slot) * STG_BYTES;                         \
        _Pragma("unroll")                                                          \
        for (int i_ = 0; i_ < 8; i_++) cp16(d_ + 2048u * i_,           pA + CH16 * i_); \
        _Pragma("unroll")                                                          \
        for (int i_ = 0; i_ < 8; i_++) cp16(d_ + A_BYTES + 2048u * i_, pB + CH16 * i_); \
        CPASYNC_MBAR_ARRIVE(mb_full + (slot) * 8);                                 \
        pA += 128; pB += 128;                                                      \
    } while (0)

#define LDSM_AB(buf, sa_, sbb_, ach_, bch_) do {                                   \
        _Pragma("unroll")                                                          \
        for (int mb_ = 0; mb_ < 4; mb_++)                                          \
            ldsm4(a[buf][mb_][0], a[buf][mb_][1], a[buf][mb_][2], a[buf][mb_][3],  \
                  (sa_) + swz(a_row + mb_ * 16, (ach_)));                          \
        _Pragma("unroll")                                                          \
        for (int nb_ = 0; nb_ < 4; nb_++)                                          \
            ldsm4(b[buf][nb_][0], b[buf][nb_][1], b[buf][nb_][2], b[buf][nb_][3],  \
                  (sbb_) + swz(b_row + nb_ * 16, (bch_)));                         \
    } while (0)

#define MMA_ALL(buf)                                                               \
        _Pragma("unroll")                                                          \
        for (int mb_ = 0; mb_ < 4; mb_++)                                          \
            _Pragma("unroll")                                                      \
            for (int nb_ = 0; nb_ < 8; nb_++)                                      \
                mma16816(acc[mb_][nb_], a[buf][mb_], &b[buf][nb_ >> 1][(nb_ & 1) * 2])

    // prologue: produce K-chunks 0, 1 into slots 0, 1
    PRODUCE(0);
    PRODUCE(1);

    float acc[4][8][4];
    #pragma unroll
    for (int i = 0; i < 4; i++)
        #pragma unroll
        for (int j = 0; j < 8; j++)
            #pragma unroll
            for (int k = 0; k < 4; k++) acc[i][j][k] = 0.0f;

    uint32_t a[2][4][4], b[2][4][4];
    int s = 0, sj = 2;   // consume slot, produce slot

    for (int it = 0; it < KITERS; ++it) {
        // ---- wait for iter it's data ----
        MBAR_WAIT(mb_full + s * 8, (pf >> s) & 1);
        pf ^= (1u << s);

        // ---- early produce: K-chunk it+2 into slot sj ----
        if (it < KITERS - 2) {
            PRODUCE(sj);
            sj = (sj == 2) ? 0 : sj + 1;
        }

        uint32_t sa  = sb + SMEM_STAGE0 + (uint32_t)s * STG_BYTES;
        uint32_t sbb = sa + A_BYTES;

        // preload k16 = 0 into buffer 0
        LDSM_AB(0, sa, sbb, a_ch0, b_ch0);

        #pragma unroll
        for (int k16 = 0; k16 < 4; k16++) {
            int cur = k16 & 1, nxt = cur ^ 1;
            if (k16 < 3) {
                // prefetch k16+1 fragments into the alternate buffer
                LDSM_AB(nxt, sa, sbb, a_ch0 + (uint32_t)(k16 + 1) * 2,
                                     b_ch0 + (uint32_t)(k16 + 1) * 2);
                if (k16 == 2) {
                    // last LDSM of stage s issued -> release for refill
                    MBAR_ARRIVE(mb_empty + s * 8);
                }
            }
            MMA_ALL(cur);
        }

        s = (s == 2) ? 0 : s + 1;
    }

    // epilogue: scale rows by beta and store
    int group = lane >> 2, t4 = lane & 3;
    #pragma unroll
    for (int mb = 0; mb < 4; mb++) {
        int r0e = m0 + wrow + mb * 16 + group;
        float b0 = g_beta[r0e];
        float b1 = g_beta[r0e + 8];
        float* o0 = out + (size_t)r0e * UU + n0 + wcol + t4 * 2;
        float* o1 = o0 + (size_t)8 * UU;
        #pragma unroll
        for (int nb = 0; nb < 8; nb++) {
            float2 v0 = make_float2(acc[mb][nb][0] * b0, acc[mb][nb][1] * b0);
            float2 v1 = make_float2(acc[mb][nb][2] * b1, acc[mb][nb][3] * b1);
            *reinterpret_cast<float2*>(o0 + nb * 8) = v0;
            *reinterpret_cast<float2*>(o1 + nb * 8) = v1;
        }
    }
#undef PRODUCE
#undef LDSM_AB
#undef MMA_ALL
}

// ---------------- launch ----------------
extern "C" void kernel_launch(void* const* d_in, const int* in_sizes, int n_in,
                              void* d_out, int out_size) {
    const float* x  = (const float*)d_in[0];
    const float* k0 = (const float*)d_in[1];
    const float* k1 = (const float*)d_in[2];
    const float* k2 = (const float*)d_in[3];
    const float* a0 = (const float*)d_in[4];
    const float* a1 = (const float*)d_in[5];
    const float* a2 = (const float*)d_in[6];
    float* out = (float*)d_out;

    prep_kernel<<<TOK + 1024, 128>>>(x, k0, k1, k2, a0, a1, a2);

    cudaFuncSetAttribute(gemm_kernel, cudaFuncAttributeMaxDynamicSharedMemorySize, SMEM_TOTAL);
    gemm_kernel<<<(TOK / BM) * (UU / BN), 128, SMEM_TOTAL>>>(out);
}